// round 1
// baseline (speedup 1.0000x reference)
#include <cuda_runtime.h>
#include <cstdint>

// ---------------------------------------------------------------------------
// Problem constants
// ---------------------------------------------------------------------------
#define BB   32
#define FEAT 512
#define SS   128
#define SP   (SS*SS)          // 16384 pixels
#define CD   8
#define KK   7

// Output layout (floats), concatenated in reference return order
#define OFF_LOGM   ((size_t)0)                         // (8,32,1,128,128)
#define OFF_LOGS   ((size_t)4194304)                   // (8,32,1,128,128)
#define OFF_SEEDS  ((size_t)8388608)                   // (7,32,8)
#define OFF_COLOUR ((size_t)8390400)                   // (32,8,128,128)
#define OFF_DELTA  ((size_t)12584704)                  // (32,2,128,128)

// ---------------------------------------------------------------------------
// Scratch (no allocations allowed -> __device__ globals)
// ---------------------------------------------------------------------------
__device__ float               g_log_s[BB * SP];        // 2 MB evolving state
__device__ unsigned long long  g_slot[KK * BB];         // packed argmax per (step,batch)

// ---------------------------------------------------------------------------
// f32x2 helpers (Blackwell packed fp32 — doubles FFMA throughput)
// ---------------------------------------------------------------------------
__device__ __forceinline__ unsigned long long pk2(float a, float b) {
    unsigned long long r;
    asm("mov.b64 %0, {%1,%2};" : "=l"(r) : "f"(a), "f"(b));
    return r;
}
__device__ __forceinline__ void upk2(unsigned long long v, float& a, float& b) {
    asm("mov.b64 {%0,%1}, %2;" : "=f"(a), "=f"(b) : "l"(v));
}
__device__ __forceinline__ unsigned long long ffma2(unsigned long long a,
                                                    unsigned long long b,
                                                    unsigned long long c) {
    unsigned long long r;
    asm("fma.rn.f32x2 %0, %1, %2, %3;" : "=l"(r) : "l"(a), "l"(b), "l"(c));
    return r;
}

// ---------------------------------------------------------------------------
// init: reset argmax slots (must happen every graph replay)
// ---------------------------------------------------------------------------
__global__ void init_kernel() {
    int i = threadIdx.x;
    if (i < KK * BB) g_slot[i] = 0ull;
}

// ---------------------------------------------------------------------------
// Block-level packed-argmax reduce + atomic publish
// key = (bits(pp) << 32) | (16383 - pixel_idx)   (pp >= 0 so bits are monotone;
// ties resolve to the LOWEST pixel index, matching jnp.argmax)
// ---------------------------------------------------------------------------
__device__ __forceinline__ void publish_argmax(unsigned long long key,
                                               unsigned long long* slot,
                                               unsigned long long* s_red,
                                               int tid) {
    #pragma unroll
    for (int o = 16; o; o >>= 1) {
        unsigned long long other = __shfl_down_sync(0xffffffffu, key, o);
        key = key > other ? key : other;
    }
    if ((tid & 31) == 0) s_red[tid >> 5] = key;
    __syncthreads();
    if (tid < 32) {
        unsigned long long v = (tid < 8) ? s_red[tid] : 0ull;
        #pragma unroll
        for (int o = 4; o; o >>= 1) {
            unsigned long long other = __shfl_down_sync(0xffffffffu, v, o);
            v = v > other ? v : other;
        }
        if (tid == 0) atomicMax(slot, v);
    }
}

// ---------------------------------------------------------------------------
// Kernel A: 1x1 conv (GEMM), colour = gate*(W.f + b) + uv, delta = x[:, -2:]
// Also seeds the step-0 argmax (scope == 1 -> pp == rand_pixel).
// Grid: 512 blocks (32 batches x 16 tiles), 256 threads, 4 pixels/thread.
// ---------------------------------------------------------------------------
__global__ void __launch_bounds__(256)
gemm_kernel(const float* __restrict__ features,
            const float* __restrict__ rand_pixel,
            const float* __restrict__ conv_w,
            const float* __restrict__ conv_b,
            const float* __restrict__ gate,
            const float* __restrict__ uv,
            float* __restrict__ out) {
    __shared__ float2 wt2[FEAT * CD];          // transposed, duplicated pairs (32 KB)
    __shared__ unsigned long long s_red[8];

    int tid = threadIdx.x;
    for (int i = tid; i < FEAT * CD; i += 256) {
        int c = i >> 3, o = i & 7;
        float w = conv_w[o * FEAT + c];
        wt2[c * CD + o] = make_float2(w, w);
    }
    __syncthreads();

    int b   = blockIdx.x >> 4;
    int pix = ((int)(blockIdx.x & 15) * 256 + tid) * 4;

    const float* fb = features + (size_t)b * FEAT * SP + pix;

    // acc[o*2+0] holds pixels {0,1}, acc[o*2+1] holds pixels {2,3} (packed f32x2)
    unsigned long long acc[16];
    #pragma unroll
    for (int i = 0; i < 16; i++) acc[i] = 0ull;

    #pragma unroll 4
    for (int c = 0; c < FEAT; c++) {
        float4 fv = *(const float4*)(fb + (size_t)c * SP);
        unsigned long long f01 = pk2(fv.x, fv.y);
        unsigned long long f23 = pk2(fv.z, fv.w);
        const ulonglong2* wr = (const ulonglong2*)(wt2 + c * CD);
        ulonglong2 wA = wr[0], wB = wr[1], wC = wr[2], wD = wr[3];
        acc[0]  = ffma2(f01, wA.x, acc[0]);  acc[1]  = ffma2(f23, wA.x, acc[1]);
        acc[2]  = ffma2(f01, wA.y, acc[2]);  acc[3]  = ffma2(f23, wA.y, acc[3]);
        acc[4]  = ffma2(f01, wB.x, acc[4]);  acc[5]  = ffma2(f23, wB.x, acc[5]);
        acc[6]  = ffma2(f01, wB.y, acc[6]);  acc[7]  = ffma2(f23, wB.y, acc[7]);
        acc[8]  = ffma2(f01, wC.x, acc[8]);  acc[9]  = ffma2(f23, wC.x, acc[9]);
        acc[10] = ffma2(f01, wC.y, acc[10]); acc[11] = ffma2(f23, wC.y, acc[11]);
        acc[12] = ffma2(f01, wD.x, acc[12]); acc[13] = ffma2(f23, wD.x, acc[13]);
        acc[14] = ffma2(f01, wD.y, acc[14]); acc[15] = ffma2(f23, wD.y, acc[15]);
    }

    float g = gate[0];
    #pragma unroll
    for (int o = 0; o < CD; o++) {
        float a0, a1, a2, a3;
        upk2(acc[o * 2 + 0], a0, a1);
        upk2(acc[o * 2 + 1], a2, a3);
        float bo = conv_b[o];
        float x0 = g * (a0 + bo), x1 = g * (a1 + bo);
        float x2 = g * (a2 + bo), x3 = g * (a3 + bo);
        float4 uvv = *(const float4*)(uv + (size_t)o * SP + pix);
        float4 col = make_float4(x0 + uvv.x, x1 + uvv.y, x2 + uvv.z, x3 + uvv.w);
        *(float4*)(out + OFF_COLOUR + (size_t)b * (CD * SP) + (size_t)o * SP + pix) = col;
        if (o >= 6) {
            *(float4*)(out + OFF_DELTA + (size_t)b * (2 * SP) + (size_t)(o - 6) * SP + pix) =
                make_float4(x0, x1, x2, x3);
        }
    }

    // step-0 argmax: pp = rand_pixel * exp(0) = rand_pixel
    float4 rv = *(const float4*)(rand_pixel + (size_t)b * SP + pix);
    float ra[4] = {rv.x, rv.y, rv.z, rv.w};
    float vmax = -1.0f; int imax = 0;
    #pragma unroll
    for (int j = 0; j < 4; j++)
        if (ra[j] > vmax) { vmax = ra[j]; imax = pix + j; }
    unsigned long long key =
        (((unsigned long long)__float_as_uint(vmax)) << 32) |
        (unsigned long long)(unsigned)(16383 - imax);
    publish_argmax(key, &g_slot[b], s_red, tid);
}

// ---------------------------------------------------------------------------
// Kernel B (x7): one SBP step. Reads finalized argmax slot[k], does the
// elementwise update, writes log_m_k[k] / log_s_k[k+1] / seeds[k], updates
// g_log_s, and publishes the argmax for step k+1.
// Grid: 512 blocks x 256 threads, 4 pixels/thread.
// ---------------------------------------------------------------------------
__global__ void __launch_bounds__(256)
step_kernel(const float* __restrict__ rand_pixel,
            const float* __restrict__ log_sigma,
            float* __restrict__ out,
            int k) {
    const float* colour = out + OFF_COLOUR;
    __shared__ float s_seed[CD];
    __shared__ unsigned long long s_red[8];

    int tid = threadIdx.x;
    int b   = blockIdx.x >> 4;
    int pix = ((int)(blockIdx.x & 15) * 256 + tid) * 4;
    size_t pbase = (size_t)b * SP + pix;

    unsigned long long slotv = g_slot[k * BB + b];
    int idx = 16383 - (int)(unsigned)(slotv & 0xffffffffull);

    if (tid < CD) {
        float sv = colour[(size_t)b * (CD * SP) + (size_t)tid * SP + idx];
        s_seed[tid] = sv;
        if ((blockIdx.x & 15) == 0)
            out[OFF_SEEDS + ((size_t)k * BB + b) * CD + tid] = sv;
    }
    __syncthreads();

    float sd[CD];
    #pragma unroll
    for (int c = 0; c < CD; c++) sd[c] = s_seed[c];

    float4 d2 = make_float4(0.f, 0.f, 0.f, 0.f);
    #pragma unroll
    for (int c = 0; c < CD; c++) {
        float4 cv = *(const float4*)(colour + (size_t)b * (CD * SP) + (size_t)c * SP + pix);
        float dx = cv.x - sd[c]; d2.x = fmaf(dx, dx, d2.x);
        float dy = cv.y - sd[c]; d2.y = fmaf(dy, dy, d2.y);
        float dz = cv.z - sd[c]; d2.z = fmaf(dz, dz, d2.z);
        float dw = cv.w - sd[c]; d2.w = fmaf(dw, dw, d2.w);
    }

    float ls[4];
    if (k == 0) {
        ls[0] = ls[1] = ls[2] = ls[3] = 0.f;
    } else {
        float4 t = *(const float4*)(g_log_s + pbase);
        ls[0] = t.x; ls[1] = t.y; ls[2] = t.z; ls[3] = t.w;
    }

    float inv_sigma = 1.0f / expf(log_sigma[0]);
    float d2a[4] = {d2.x, d2.y, d2.z, d2.w};
    float lm[4], nls[4];
    #pragma unroll
    for (int j = 0; j < 4; j++) {
        float z    = d2a[j] * inv_sigma;
        float araw = expf(-z);
        float alpha, la;
        if (araw < 0.01f)      { alpha = 0.01f; la = -4.6051702f;  }   // log(0.01)
        else if (araw > 0.99f) { alpha = 0.99f; la = -0.01005034f; }   // log(0.99)
        else                   { alpha = araw;  la = -z;           }
        lm[j]  = ls[j] + la;
        nls[j] = ls[j] + log1pf(-alpha);
    }

    *(float4*)(out + OFF_LOGM + (size_t)k * (BB * SP) + pbase) =
        make_float4(lm[0], lm[1], lm[2], lm[3]);
    *(float4*)(out + OFF_LOGS + (size_t)(k + 1) * (BB * SP) + pbase) =
        make_float4(nls[0], nls[1], nls[2], nls[3]);
    if (k == 0)
        *(float4*)(out + OFF_LOGS + pbase) = make_float4(0.f, 0.f, 0.f, 0.f);
    if (k == KK - 1)
        *(float4*)(out + OFF_LOGM + (size_t)KK * (BB * SP) + pbase) =
            make_float4(nls[0], nls[1], nls[2], nls[3]);

    if (k < KK - 1) {
        *(float4*)(g_log_s + pbase) = make_float4(nls[0], nls[1], nls[2], nls[3]);
        float4 rv = *(const float4*)(rand_pixel + pbase);
        float ra[4] = {rv.x, rv.y, rv.z, rv.w};
        float vmax = -1.0f; int imax = 0;
        #pragma unroll
        for (int j = 0; j < 4; j++) {
            float pp = ra[j] * expf(nls[j]);
            if (pp > vmax) { vmax = pp; imax = pix + j; }
        }
        unsigned long long key =
            (((unsigned long long)__float_as_uint(vmax)) << 32) |
            (unsigned long long)(unsigned)(16383 - imax);
        publish_argmax(key, &g_slot[(k + 1) * BB + b], s_red, tid);
    }
}

// ---------------------------------------------------------------------------
// Launch
// ---------------------------------------------------------------------------
extern "C" void kernel_launch(void* const* d_in, const int* in_sizes, int n_in,
                              void* d_out, int out_size) {
    const float* features   = (const float*)d_in[0];
    const float* rand_pixel = (const float*)d_in[1];
    const float* conv_w     = (const float*)d_in[2];
    const float* conv_b     = (const float*)d_in[3];
    const float* gate       = (const float*)d_in[4];
    const float* log_sigma  = (const float*)d_in[5];
    const float* uv         = (const float*)d_in[6];
    float* out = (float*)d_out;

    init_kernel<<<1, 256>>>();
    gemm_kernel<<<BB * 16, 256>>>(features, rand_pixel, conv_w, conv_b, gate, uv, out);
    for (int k = 0; k < KK; k++)
        step_kernel<<<BB * 16, 256>>>(rand_pixel, log_sigma, out, k);
}